// round 13
// baseline (speedup 1.0000x reference)
#include <cuda_runtime.h>
#include <cstdint>

#define BATCH   4
#define TSEQ    4096
#define CDIM    512
#define HDIM    64
#define BT_TOTAL (BATCH * TSEQ)   // 16384
#define QTILE   128
#define KTILE   32
#define NSPLIT  4
#define KEYS_PER_SPLIT (TSEQ / NSPLIT)     // 1024
#define NT      (KEYS_PER_SPLIT / KTILE)   // 32

#define KSTR2   36   // K raw row stride (float2): 32 entries used; banks 8g+8k+2tg distinct
#define VSTR2   20   // V^T row stride (float2): 16 entries used
#define WSTR4   20   // W row stride (float4)
#define XSTR    36   // xs row stride (floats)

typedef unsigned long long u64;

// ---- tf32 helpers ----
__device__ __forceinline__ float tf32_hi(float a) {
    unsigned u;
    asm("cvt.rna.tf32.f32 %0, %1;" : "=r"(u) : "f"(a));
    return __uint_as_float(u);
}
__device__ __forceinline__ void mma_tf32(
    float& c0, float& c1, float& c2, float& c3,
    float a0, float a1, float a2, float a3,
    float b0, float b1)
{
    unsigned A0 = __float_as_uint(a0), A1 = __float_as_uint(a1);
    unsigned A2 = __float_as_uint(a2), A3 = __float_as_uint(a3);
    unsigned B0 = __float_as_uint(b0), B1 = __float_as_uint(b1);
    asm("mma.sync.aligned.m16n8k8.row.col.f32.tf32.tf32.f32 "
        "{%0,%1,%2,%3},{%4,%5,%6,%7},{%8,%9},{%0,%1,%2,%3};"
        : "+f"(c0), "+f"(c1), "+f"(c2), "+f"(c3)
        : "r"(A0), "r"(A1), "r"(A2), "r"(A3), "r"(B0), "r"(B1));
}

// Scratch (static device arrays per allocation rules).
__device__ float g_q[BT_TOTAL * HDIM];
__device__ float g_k[BT_TOTAL * HDIM];
__device__ float g_v[BT_TOTAL * HDIM];
__device__ float g_wt[3][HDIM][CDIM];      // transposed weights [mat][n][k]
// split-KV partials
__device__ float g_pacc[NSPLIT][BT_TOTAL][HDIM];
__device__ float g_pm[NSPLIT][BT_TOTAL];
__device__ float g_pl[NSPLIT][BT_TOTAL];

// ---------------------------------------------------------------------------
// Transpose W [512][64] -> g_wt [64][512].  grid (128, 3), block 256.
// ---------------------------------------------------------------------------
__global__ __launch_bounds__(256) void transpose_w_kernel(
    const float* __restrict__ Wq,
    const float* __restrict__ Wk,
    const float* __restrict__ Wv)
{
    const int mat = blockIdx.y;
    const float* __restrict__ W = (mat == 0) ? Wq : (mat == 1) ? Wk : Wv;
    const int idx = blockIdx.x * 256 + threadIdx.x;   // 0..32767
    const int k = idx & (CDIM - 1);
    const int n = idx >> 9;
    g_wt[mat][n][k] = W[k * HDIM + n];
}

// ---------------------------------------------------------------------------
// Tensor-core projection GEMM, 3xTF32 (unchanged from R10).
// ---------------------------------------------------------------------------
__global__ __launch_bounds__(128) void proj_mma_kernel(const float* __restrict__ x)
{
    __shared__ float  xs[128 * XSTR];
    __shared__ float4 Wsm[HDIM * WSTR4];

    const int mat  = blockIdx.y;
    float* __restrict__ out = (mat == 0) ? g_q : (mat == 1) ? g_k : g_v;
    const int row0 = blockIdx.x * 128;
    const int tid  = threadIdx.x;
    const int w    = tid >> 5;
    const int ln   = tid & 31;
    const int g    = ln >> 2;
    const int tg   = ln & 3;

    float o[2][8][4];
    #pragma unroll
    for (int m = 0; m < 2; m++)
        #pragma unroll
        for (int n = 0; n < 8; n++)
            #pragma unroll
            for (int i = 0; i < 4; i++) o[m][n][i] = 0.0f;

    #pragma unroll 1
    for (int k0 = 0; k0 < CDIM; k0 += 32) {
        __syncthreads();
        #pragma unroll
        for (int p = 0; p < 8; p++) {
            const int task = p * 128 + tid;
            const int r    = task >> 3;
            const int cg   = task & 7;
            float4 v = *reinterpret_cast<const float4*>(
                &x[(long)(row0 + r) * CDIM + k0 + cg * 4]);
            *reinterpret_cast<float4*>(&xs[r * XSTR + cg * 4]) = v;
        }
        #pragma unroll
        for (int p = 0; p < 2; p++) {
            const int task = p * 128 + tid;
            const int n    = task >> 2;
            const int c    = task & 3;
            const float* wr = &g_wt[mat][n][k0 + c * 8];
            float4 fa = *reinterpret_cast<const float4*>(wr);
            float4 fb = *reinterpret_cast<const float4*>(wr + 4);
            float a_[4] = {fa.x, fa.y, fa.z, fa.w};
            float b_[4] = {fb.x, fb.y, fb.z, fb.w};
            float4* dst = &Wsm[n * WSTR4 + c * 4];
            #pragma unroll
            for (int q = 0; q < 4; q++) {
                float ha = tf32_hi(a_[q]);
                float hb = tf32_hi(b_[q]);
                dst[q] = make_float4(ha, hb, a_[q] - ha, b_[q] - hb);
            }
        }
        __syncthreads();

        #pragma unroll
        for (int kb = 0; kb < 4; kb++) {
            float ah[2][4], al[2][4];
            #pragma unroll
            for (int m = 0; m < 2; m++) {
                const int r = w * 32 + m * 16 + g;
                float a0 = xs[r * XSTR + kb * 8 + tg];
                float a1 = xs[(r + 8) * XSTR + kb * 8 + tg];
                float a2 = xs[r * XSTR + kb * 8 + tg + 4];
                float a3 = xs[(r + 8) * XSTR + kb * 8 + tg + 4];
                ah[m][0] = tf32_hi(a0); al[m][0] = a0 - ah[m][0];
                ah[m][1] = tf32_hi(a1); al[m][1] = a1 - ah[m][1];
                ah[m][2] = tf32_hi(a2); al[m][2] = a2 - ah[m][2];
                ah[m][3] = tf32_hi(a3); al[m][3] = a3 - ah[m][3];
            }
            #pragma unroll
            for (int n = 0; n < 8; n++) {
                float4 wp = Wsm[(n * 8 + g) * WSTR4 + kb * 4 + tg];
                #pragma unroll
                for (int m = 0; m < 2; m++) {
                    mma_tf32(o[m][n][0], o[m][n][1], o[m][n][2], o[m][n][3],
                             ah[m][0], ah[m][1], ah[m][2], ah[m][3], wp.x, wp.y);
                    mma_tf32(o[m][n][0], o[m][n][1], o[m][n][2], o[m][n][3],
                             al[m][0], al[m][1], al[m][2], al[m][3], wp.x, wp.y);
                    mma_tf32(o[m][n][0], o[m][n][1], o[m][n][2], o[m][n][3],
                             ah[m][0], ah[m][1], ah[m][2], ah[m][3], wp.z, wp.w);
                }
            }
        }
    }

    const float scale = (mat == 0) ? 8.0f : 1.0f;
    #pragma unroll
    for (int m = 0; m < 2; m++) {
        const long rowA = (long)(row0 + w * 32 + m * 16 + g);
        const long rowB = rowA + 8;
        #pragma unroll
        for (int n = 0; n < 8; n++) {
            const int c = n * 8 + 2 * tg;
            *reinterpret_cast<float2*>(&out[rowA * HDIM + c]) =
                make_float2(o[m][n][0] * scale, o[m][n][1] * scale);
            *reinterpret_cast<float2*>(&out[rowB * HDIM + c]) =
                make_float2(o[m][n][2] * scale, o[m][n][3] * scale);
        }
    }
}

// ---------------------------------------------------------------------------
// mma.sync flash attention. QK = 3xTF32 (K split inline from raw smem),
// PV = 1xTF32. Single-buffered; occupancy-first: smem 68.6 KB + regs<=170
// -> 3 CTAs/SM = 3 warps/SMSP to hide mma/softmax dependency latency.
// grid (TSEQ/QTILE, BATCH, NSPLIT), block 128.
// smem: K2 1152 f2 | VP2 1280 f2 | QA 2048 f4 | P2 2048 f2 = 68,608 B.
// ---------------------------------------------------------------------------
__global__ __launch_bounds__(128, 3) void attn_mma_kernel()
{
    extern __shared__ float4 sm4[];
    float2* K2  = reinterpret_cast<float2*>(sm4);          // 1152 f2 (raw K pairs)
    float2* VP2 = reinterpret_cast<float2*>(sm4 + 576);    // 1280 f2 (tf32-hi V pairs)
    float4* QA  = sm4 + 1216;                              // 2048 f4 (raw Q A-frags)
    float2* P2  = reinterpret_cast<float2*>(sm4 + 3264);   // 2048 f2 (P pairs)

    const int b     = blockIdx.y;
    const int split = blockIdx.z;
    const int q0    = blockIdx.x * QTILE;
    const int tid   = threadIdx.x;
    const int w     = tid >> 5;
    const int ln    = tid & 31;
    const int g     = ln >> 2;
    const int tg    = ln & 3;

    const float* __restrict__ kb = &g_k[(long)b * TSEQ * HDIM];
    const float* __restrict__ vb = &g_v[(long)b * TSEQ * HDIM];

    // ---- stage Q (raw, A-fragment packed) ----
    #pragma unroll
    for (int i = 0; i < 16; i++) {
        const int e  = tid * 16 + i;
        const int mb = e >> 8;
        const int k  = (e >> 5) & 7;
        const int t2 = (e >> 3) & 3;
        const int g2 = e & 7;
        const int r  = (mb >> 1) * 32 + (mb & 1) * 16 + g2;
        const int c  = k * 8 + t2;
        const float* q0p = &g_q[((long)b * TSEQ + q0 + r) * HDIM];
        const float* q1p = &g_q[((long)b * TSEQ + q0 + r + 8) * HDIM];
        QA[e] = make_float4(q0p[c], q1p[c], q0p[c + 4], q1p[c + 4]);
    }

    float o[2][8][4];
    #pragma unroll
    for (int m = 0; m < 2; m++)
        #pragma unroll
        for (int n = 0; n < 8; n++)
            #pragma unroll
            for (int i = 0; i < 4; i++) o[m][n][i] = 0.0f;
    float mr[2][2], lr[2][2];
    #pragma unroll
    for (int m = 0; m < 2; m++) {
        mr[m][0] = mr[m][1] = -1e30f;
        lr[m][0] = lr[m][1] = 0.0f;
    }

    #pragma unroll 1
    for (int t = 0; t < NT; t++) {
        const int t0 = split * KEYS_PER_SPLIT + t * KTILE;
        __syncthreads();

        // ---- stage K raw pairs: 256 tasks (32 keys x 8 k-blocks) ----
        #pragma unroll
        for (int p = 0; p < 2; p++) {
            const int task = p * 128 + tid;
            const int key  = task >> 3;
            const int c    = task & 7;
            const float* kr = &kb[(long)(t0 + key) * HDIM + c * 8];
            float4 fa = *reinterpret_cast<const float4*>(kr);
            float4 fb = *reinterpret_cast<const float4*>(kr + 4);
            float a_[4] = {fa.x, fa.y, fa.z, fa.w};
            float b_[4] = {fb.x, fb.y, fb.z, fb.w};
            float2* dst = &K2[key * KSTR2 + c * 4];
            #pragma unroll
            for (int q = 0; q < 4; q++)
                dst[q] = make_float2(a_[q], b_[q]);
        }
        // ---- stage V^T (tf32-hi only): 256 tasks ----
        #pragma unroll
        for (int p = 0; p < 2; p++) {
            const int task = p * 128 + tid;
            const int bk   = task >> 4;
            const int h4   = (task & 15) * 4;
            const int kk   = bk >> 2;
            const int tt   = bk & 3;
            const int keyA = kk * 8 + tt;
            const float* va_ = &vb[(long)(t0 + keyA) * HDIM + h4];
            const float* vb_ = &vb[(long)(t0 + keyA + 4) * HDIM + h4];
            float4 fa = *reinterpret_cast<const float4*>(va_);
            float4 fb = *reinterpret_cast<const float4*>(vb_);
            float a_[4] = {fa.x, fa.y, fa.z, fa.w};
            float b_[4] = {fb.x, fb.y, fb.z, fb.w};
            #pragma unroll
            for (int q = 0; q < 4; q++) {
                VP2[(h4 + q) * VSTR2 + kk * 4 + tt] =
                    make_float2(tf32_hi(a_[q]), tf32_hi(b_[q]));
            }
        }
        __syncthreads();

        // ---- QK: S = Q K^T (3xTF32, K split inline) ----
        float s[2][4][4];
        #pragma unroll
        for (int m = 0; m < 2; m++)
            #pragma unroll
            for (int n = 0; n < 4; n++)
                #pragma unroll
                for (int i = 0; i < 4; i++) s[m][n][i] = 0.0f;

        #pragma unroll
        for (int k = 0; k < 8; k++) {
            float qh[2][4], ql[2][4];
            #pragma unroll
            for (int m = 0; m < 2; m++) {
                float4 qa = QA[(w * 2 + m) * 256 + k * 32 + tg * 8 + g];
                float v_[4] = {qa.x, qa.y, qa.z, qa.w};
                #pragma unroll
                for (int q = 0; q < 4; q++) {
                    qh[m][q] = tf32_hi(v_[q]);
                    ql[m][q] = v_[q] - qh[m][q];
                }
            }
            const float2* kbase = &K2[g * KSTR2 + k * 4 + tg];
            #pragma unroll
            for (int n = 0; n < 4; n++) {
                float2 kr = kbase[n * 8 * KSTR2];
                float khA = tf32_hi(kr.x), klA = kr.x - khA;
                float khB = tf32_hi(kr.y), klB = kr.y - khB;
                #pragma unroll
                for (int m = 0; m < 2; m++) {
                    mma_tf32(s[m][n][0], s[m][n][1], s[m][n][2], s[m][n][3],
                             qh[m][0], qh[m][1], qh[m][2], qh[m][3], khA, khB);
                    mma_tf32(s[m][n][0], s[m][n][1], s[m][n][2], s[m][n][3],
                             ql[m][0], ql[m][1], ql[m][2], ql[m][3], khA, khB);
                    mma_tf32(s[m][n][0], s[m][n][1], s[m][n][2], s[m][n][3],
                             qh[m][0], qh[m][1], qh[m][2], qh[m][3], klA, klB);
                }
            }
        }

        // ---- online softmax ----
        #pragma unroll
        for (int m = 0; m < 2; m++) {
            const int mb = w * 2 + m;
            float mxA = -1e30f, mxB = -1e30f;
            #pragma unroll
            for (int n = 0; n < 4; n++) {
                mxA = fmaxf(mxA, fmaxf(s[m][n][0], s[m][n][1]));
                mxB = fmaxf(mxB, fmaxf(s[m][n][2], s[m][n][3]));
            }
            mxA = fmaxf(mxA, __shfl_xor_sync(0xffffffffu, mxA, 1));
            mxA = fmaxf(mxA, __shfl_xor_sync(0xffffffffu, mxA, 2));
            mxB = fmaxf(mxB, __shfl_xor_sync(0xffffffffu, mxB, 1));
            mxB = fmaxf(mxB, __shfl_xor_sync(0xffffffffu, mxB, 2));

            const float nmA = fmaxf(mr[m][0], mxA);
            const float nmB = fmaxf(mr[m][1], mxB);
            const float alA = __expf(mr[m][0] - nmA);
            const float alB = __expf(mr[m][1] - nmB);
            mr[m][0] = nmA; mr[m][1] = nmB;

            float lsA = 0.0f, lsB = 0.0f;
            #pragma unroll
            for (int n = 0; n < 4; n++) {
                float p0 = __expf(s[m][n][0] - nmA);
                float p1 = __expf(s[m][n][1] - nmA);
                float p2 = __expf(s[m][n][2] - nmB);
                float p3 = __expf(s[m][n][3] - nmB);
                lsA += p0 + p1;
                lsB += p2 + p3;
                const int c = n * 8 + 2 * tg;
                P2[mb * 256 + c * 8 + g]       = make_float2(p0, p2);
                P2[mb * 256 + (c + 1) * 8 + g] = make_float2(p1, p3);
            }
            lsA += __shfl_xor_sync(0xffffffffu, lsA, 1);
            lsA += __shfl_xor_sync(0xffffffffu, lsA, 2);
            lsB += __shfl_xor_sync(0xffffffffu, lsB, 1);
            lsB += __shfl_xor_sync(0xffffffffu, lsB, 2);
            lr[m][0] = lr[m][0] * alA + lsA;
            lr[m][1] = lr[m][1] * alB + lsB;

            #pragma unroll
            for (int n = 0; n < 8; n++) {
                o[m][n][0] *= alA; o[m][n][1] *= alA;
                o[m][n][2] *= alB; o[m][n][3] *= alB;
            }
        }
        __syncwarp();

        // ---- PV: O += P V (1xTF32) ----
        #pragma unroll
        for (int k = 0; k < 4; k++) {
            float ah[2][4];
            #pragma unroll
            for (int m = 0; m < 2; m++) {
                const int mb = w * 2 + m;
                float2 pA = P2[mb * 256 + (k * 8 + tg) * 8 + g];
                float2 pB = P2[mb * 256 + (k * 8 + tg + 4) * 8 + g];
                ah[m][0] = tf32_hi(pA.x);
                ah[m][1] = tf32_hi(pA.y);
                ah[m][2] = tf32_hi(pB.x);
                ah[m][3] = tf32_hi(pB.y);
            }
            const float2* vbase = &VP2[g * VSTR2 + k * 4 + tg];
            #pragma unroll
            for (int n = 0; n < 8; n++) {
                float2 vp = vbase[n * 8 * VSTR2];
                #pragma unroll
                for (int m = 0; m < 2; m++) {
                    mma_tf32(o[m][n][0], o[m][n][1], o[m][n][2], o[m][n][3],
                             ah[m][0], ah[m][1], ah[m][2], ah[m][3], vp.x, vp.y);
                }
            }
        }
    }

    // ---- epilogue: write unnormalized partials + (m, l) ----
    #pragma unroll
    for (int m = 0; m < 2; m++) {
        const long rowA = (long)b * TSEQ + q0 + w * 32 + m * 16 + g;
        const long rowB = rowA + 8;
        #pragma unroll
        for (int n = 0; n < 8; n++) {
            const int c = n * 8 + 2 * tg;
            *reinterpret_cast<float2*>(&g_pacc[split][rowA][c]) =
                make_float2(o[m][n][0], o[m][n][1]);
            *reinterpret_cast<float2*>(&g_pacc[split][rowB][c]) =
                make_float2(o[m][n][2], o[m][n][3]);
        }
        if (tg == 0) {
            g_pm[split][rowA] = mr[m][0];
            g_pl[split][rowA] = lr[m][0];
            g_pm[split][rowB] = mr[m][1];
            g_pl[split][rowB] = lr[m][1];
        }
    }
}

// ---------------------------------------------------------------------------
// Combine split-KV partials.
// ---------------------------------------------------------------------------
__global__ __launch_bounds__(128) void combine_kernel(float* __restrict__ out)
{
    const long row = (long)blockIdx.x * 128 + threadIdx.x;

    float m[NSPLIT], w[NSPLIT];
    float M = -1e30f;
    #pragma unroll
    for (int i = 0; i < NSPLIT; i++) {
        m[i] = g_pm[i][row];
        M = fmaxf(M, m[i]);
    }
    float L = 0.0f;
    #pragma unroll
    for (int i = 0; i < NSPLIT; i++) {
        w[i] = __expf(m[i] - M);
        L += w[i] * g_pl[i][row];
    }
    const float inv = 1.0f / L;

    float* __restrict__ orow = &out[row * HDIM];
    #pragma unroll
    for (int h = 0; h < HDIM; h += 4) {
        float4 a = make_float4(0.f, 0.f, 0.f, 0.f);
        #pragma unroll
        for (int i = 0; i < NSPLIT; i++) {
            float4 p = *reinterpret_cast<const float4*>(&g_pacc[i][row][h]);
            a.x += w[i] * p.x;
            a.y += w[i] * p.y;
            a.z += w[i] * p.z;
            a.w += w[i] * p.w;
        }
        a.x *= inv; a.y *= inv; a.z *= inv; a.w *= inv;
        *reinterpret_cast<float4*>(&orow[h]) = a;
    }
}

// ---------------------------------------------------------------------------
extern "C" void kernel_launch(void* const* d_in, const int* in_sizes, int n_in,
                              void* d_out, int out_size)
{
    const float* x  = (const float*)d_in[0];
    const float* Wq = (const float*)d_in[1];
    const float* Wk = (const float*)d_in[2];
    const float* Wv = (const float*)d_in[3];
    float* out = (float*)d_out;

    transpose_w_kernel<<<dim3(128, 3), 256>>>(Wq, Wk, Wv);

    proj_mma_kernel<<<dim3(BT_TOTAL / 128, 3), 128>>>(x);

    const int smem_bytes = 4288 * 16;   // 68,608 B -> 3 CTAs/SM
    static bool attr_set = false;
    if (!attr_set) {
        cudaFuncSetAttribute(attn_mma_kernel,
                             cudaFuncAttributeMaxDynamicSharedMemorySize, smem_bytes);
        attr_set = true;
    }
    dim3 ag(TSEQ / QTILE, BATCH, NSPLIT);
    attn_mma_kernel<<<ag, 128, smem_bytes>>>();

    combine_kernel<<<BT_TOTAL / 128, 128>>>(out);
}

// round 14
// speedup vs baseline: 1.8707x; 1.8707x over previous
#include <cuda_runtime.h>
#include <cuda_fp16.h>
#include <cstdint>

#define BATCH   4
#define TSEQ    4096
#define CDIM    512
#define HDIM    64
#define BT_TOTAL (BATCH * TSEQ)   // 16384
#define QTILE   128
#define KTILE   32
#define NSPLIT  2
#define KEYS_PER_SPLIT (TSEQ / NSPLIT)     // 2048
#define NT      (KEYS_PER_SPLIT / KTILE)   // 64

#define KVSTRU2 20   // K/V row stride in uint2 (16 used): read banks 8g+2tg distinct
#define PSTRU2  12   // P row stride in uint2 (8 used): read banks 24tg+2g distinct
#define WSTR4   20
#define XSTR    36

typedef unsigned int uint32;

// ---- tf32 helpers (proj kernel) ----
__device__ __forceinline__ float tf32_hi(float a) {
    unsigned u;
    asm("cvt.rna.tf32.f32 %0, %1;" : "=r"(u) : "f"(a));
    return __uint_as_float(u);
}
__device__ __forceinline__ void mma_tf32(
    float& c0, float& c1, float& c2, float& c3,
    float a0, float a1, float a2, float a3,
    float b0, float b1)
{
    unsigned A0 = __float_as_uint(a0), A1 = __float_as_uint(a1);
    unsigned A2 = __float_as_uint(a2), A3 = __float_as_uint(a3);
    unsigned B0 = __float_as_uint(b0), B1 = __float_as_uint(b1);
    asm("mma.sync.aligned.m16n8k8.row.col.f32.tf32.tf32.f32 "
        "{%0,%1,%2,%3},{%4,%5,%6,%7},{%8,%9},{%0,%1,%2,%3};"
        : "+f"(c0), "+f"(c1), "+f"(c2), "+f"(c3)
        : "r"(A0), "r"(A1), "r"(A2), "r"(A3), "r"(B0), "r"(B1));
}

// ---- fp16 helpers (attn kernel) ----
__device__ __forceinline__ uint32 pkh2(float a, float b) {
    __half2 h = __floats2half2_rn(a, b);
    return *reinterpret_cast<uint32*>(&h);
}
__device__ __forceinline__ float f16lo(float a) {
    return a - __half2float(__float2half_rn(a));
}
__device__ __forceinline__ void mma_f16(
    float& c0, float& c1, float& c2, float& c3,
    uint32 a0, uint32 a1, uint32 a2, uint32 a3,
    uint32 b0, uint32 b1)
{
    asm("mma.sync.aligned.m16n8k16.row.col.f32.f16.f16.f32 "
        "{%0,%1,%2,%3},{%4,%5,%6,%7},{%8,%9},{%0,%1,%2,%3};"
        : "+f"(c0), "+f"(c1), "+f"(c2), "+f"(c3)
        : "r"(a0), "r"(a1), "r"(a2), "r"(a3), "r"(b0), "r"(b1));
}

// Scratch (static device arrays per allocation rules).
__device__ float g_q[BT_TOTAL * HDIM];
__device__ float g_k[BT_TOTAL * HDIM];
__device__ float g_v[BT_TOTAL * HDIM];
__device__ float g_wt[3][HDIM][CDIM];
// split-KV partials
__device__ float g_pacc[NSPLIT][BT_TOTAL][HDIM];
__device__ float g_pm[NSPLIT][BT_TOTAL];
__device__ float g_pl[NSPLIT][BT_TOTAL];

// ---------------------------------------------------------------------------
// Transpose W [512][64] -> g_wt [64][512].
// ---------------------------------------------------------------------------
__global__ __launch_bounds__(256) void transpose_w_kernel(
    const float* __restrict__ Wq,
    const float* __restrict__ Wk,
    const float* __restrict__ Wv)
{
    const int mat = blockIdx.y;
    const float* __restrict__ W = (mat == 0) ? Wq : (mat == 1) ? Wk : Wv;
    const int idx = blockIdx.x * 256 + threadIdx.x;
    const int k = idx & (CDIM - 1);
    const int n = idx >> 9;
    g_wt[mat][n][k] = W[k * HDIM + n];
}

// ---------------------------------------------------------------------------
// Tensor-core projection GEMM, 3xTF32 (unchanged from R10).
// ---------------------------------------------------------------------------
__global__ __launch_bounds__(128) void proj_mma_kernel(const float* __restrict__ x)
{
    __shared__ float  xs[128 * XSTR];
    __shared__ float4 Wsm[HDIM * WSTR4];

    const int mat  = blockIdx.y;
    float* __restrict__ out = (mat == 0) ? g_q : (mat == 1) ? g_k : g_v;
    const int row0 = blockIdx.x * 128;
    const int tid  = threadIdx.x;
    const int w    = tid >> 5;
    const int ln   = tid & 31;
    const int g    = ln >> 2;
    const int tg   = ln & 3;

    float o[2][8][4];
    #pragma unroll
    for (int m = 0; m < 2; m++)
        #pragma unroll
        for (int n = 0; n < 8; n++)
            #pragma unroll
            for (int i = 0; i < 4; i++) o[m][n][i] = 0.0f;

    #pragma unroll 1
    for (int k0 = 0; k0 < CDIM; k0 += 32) {
        __syncthreads();
        #pragma unroll
        for (int p = 0; p < 8; p++) {
            const int task = p * 128 + tid;
            const int r    = task >> 3;
            const int cg   = task & 7;
            float4 v = *reinterpret_cast<const float4*>(
                &x[(long)(row0 + r) * CDIM + k0 + cg * 4]);
            *reinterpret_cast<float4*>(&xs[r * XSTR + cg * 4]) = v;
        }
        #pragma unroll
        for (int p = 0; p < 2; p++) {
            const int task = p * 128 + tid;
            const int n    = task >> 2;
            const int c    = task & 3;
            const float* wr = &g_wt[mat][n][k0 + c * 8];
            float4 fa = *reinterpret_cast<const float4*>(wr);
            float4 fb = *reinterpret_cast<const float4*>(wr + 4);
            float a_[4] = {fa.x, fa.y, fa.z, fa.w};
            float b_[4] = {fb.x, fb.y, fb.z, fb.w};
            float4* dst = &Wsm[n * WSTR4 + c * 4];
            #pragma unroll
            for (int q = 0; q < 4; q++) {
                float ha = tf32_hi(a_[q]);
                float hb = tf32_hi(b_[q]);
                dst[q] = make_float4(ha, hb, a_[q] - ha, b_[q] - hb);
            }
        }
        __syncthreads();

        #pragma unroll
        for (int kb = 0; kb < 4; kb++) {
            float ah[2][4], al[2][4];
            #pragma unroll
            for (int m = 0; m < 2; m++) {
                const int r = w * 32 + m * 16 + g;
                float a0 = xs[r * XSTR + kb * 8 + tg];
                float a1 = xs[(r + 8) * XSTR + kb * 8 + tg];
                float a2 = xs[r * XSTR + kb * 8 + tg + 4];
                float a3 = xs[(r + 8) * XSTR + kb * 8 + tg + 4];
                ah[m][0] = tf32_hi(a0); al[m][0] = a0 - ah[m][0];
                ah[m][1] = tf32_hi(a1); al[m][1] = a1 - ah[m][1];
                ah[m][2] = tf32_hi(a2); al[m][2] = a2 - ah[m][2];
                ah[m][3] = tf32_hi(a3); al[m][3] = a3 - ah[m][3];
            }
            #pragma unroll
            for (int n = 0; n < 8; n++) {
                float4 wp = Wsm[(n * 8 + g) * WSTR4 + kb * 4 + tg];
                #pragma unroll
                for (int m = 0; m < 2; m++) {
                    mma_tf32(o[m][n][0], o[m][n][1], o[m][n][2], o[m][n][3],
                             ah[m][0], ah[m][1], ah[m][2], ah[m][3], wp.x, wp.y);
                    mma_tf32(o[m][n][0], o[m][n][1], o[m][n][2], o[m][n][3],
                             al[m][0], al[m][1], al[m][2], al[m][3], wp.x, wp.y);
                    mma_tf32(o[m][n][0], o[m][n][1], o[m][n][2], o[m][n][3],
                             ah[m][0], ah[m][1], ah[m][2], ah[m][3], wp.z, wp.w);
                }
            }
        }
    }

    const float scale = (mat == 0) ? 8.0f : 1.0f;
    #pragma unroll
    for (int m = 0; m < 2; m++) {
        const long rowA = (long)(row0 + w * 32 + m * 16 + g);
        const long rowB = rowA + 8;
        #pragma unroll
        for (int n = 0; n < 8; n++) {
            const int c = n * 8 + 2 * tg;
            *reinterpret_cast<float2*>(&out[rowA * HDIM + c]) =
                make_float2(o[m][n][0] * scale, o[m][n][1] * scale);
            *reinterpret_cast<float2*>(&out[rowB * HDIM + c]) =
                make_float2(o[m][n][2] * scale, o[m][n][3] * scale);
        }
    }
}

// ---------------------------------------------------------------------------
// Flash attention on fp16 HMMA m16n8k16. QK = 3-term fp16 split (== 3xTF32
// accuracy: same 11-bit mantissa), PV = 1x fp16 (== 1xTF32 accuracy).
// Half the mma instructions of the tf32 version. R10 structure: single
// buffer, register prefetch of next tile. grid (TSEQ/128, BATCH, NSPLIT).
// smem = 64 KB: QAh/QAl 2x16K | Kh/Kl 2x5K | Vh 10K | P2h 12K.
// ---------------------------------------------------------------------------
__global__ __launch_bounds__(128) void attn_mma_kernel()
{
    extern __shared__ uint4 smu[];
    uint4* QAh = smu;                                      // 1024 uint4
    uint4* QAl = smu + 1024;                               // 1024 uint4
    uint2* Kh  = reinterpret_cast<uint2*>(smu + 2048);     // 640 uint2
    uint2* Kl  = Kh + 640;                                 // 640
    uint2* Vh  = Kl + 640;                                 // 1280
    uint2* P2h = Vh + 1280;                                // 1536 (8 mb x 16r x 12)

    const int b     = blockIdx.y;
    const int split = blockIdx.z;
    const int q0    = blockIdx.x * QTILE;
    const int tid   = threadIdx.x;
    const int w     = tid >> 5;
    const int ln    = tid & 31;
    const int g     = ln >> 2;
    const int tg    = ln & 3;

    const float* __restrict__ kb = &g_k[(long)b * TSEQ * HDIM];
    const float* __restrict__ vb = &g_v[(long)b * TSEQ * HDIM];

    // K staging indices (2 tasks per thread: 32 keys x 8 col-blocks)
    const int kkey0 = tid >> 3, kc0 = tid & 7;
    const int kkey1 = (128 + tid) >> 3, kc1 = (128 + tid) & 7;
    // V staging: 1 task per thread: adjacent-key pair k2, 8-h block
    const int vk2 = tid >> 3;            // 0..15
    const int vh8 = (tid & 7) * 8;       // 0..56

    // ---- stage Q: entry e = mb*128 + kap*32 + g*4 + tg ----
    #pragma unroll
    for (int i = 0; i < 8; i++) {
        const int e   = tid * 8 + i;
        const int mb  = e >> 7;
        const int kap = (e >> 5) & 3;
        const int gg  = (e >> 2) & 7;
        const int tt  = e & 3;
        const int r   = (mb >> 1) * 32 + (mb & 1) * 16 + gg;
        const int c   = kap * 16 + 2 * tt;
        const float* r0p = &g_q[((long)b * TSEQ + q0 + r) * HDIM];
        const float* r1p = &g_q[((long)b * TSEQ + q0 + r + 8) * HDIM];
        float2 q00 = *reinterpret_cast<const float2*>(&r0p[c]);
        float2 q10 = *reinterpret_cast<const float2*>(&r1p[c]);
        float2 q01 = *reinterpret_cast<const float2*>(&r0p[c + 8]);
        float2 q11 = *reinterpret_cast<const float2*>(&r1p[c + 8]);
        QAh[e] = make_uint4(pkh2(q00.x, q00.y), pkh2(q10.x, q10.y),
                            pkh2(q01.x, q01.y), pkh2(q11.x, q11.y));
        QAl[e] = make_uint4(pkh2(f16lo(q00.x), f16lo(q00.y)),
                            pkh2(f16lo(q10.x), f16lo(q10.y)),
                            pkh2(f16lo(q01.x), f16lo(q01.y)),
                            pkh2(f16lo(q11.x), f16lo(q11.y)));
    }

    float o[2][8][4];
    #pragma unroll
    for (int m = 0; m < 2; m++)
        #pragma unroll
        for (int n = 0; n < 8; n++)
            #pragma unroll
            for (int i = 0; i < 4; i++) o[m][n][i] = 0.0f;
    float mr[2][2], lr[2][2];
    #pragma unroll
    for (int m = 0; m < 2; m++) {
        mr[m][0] = mr[m][1] = -1e30f;
        lr[m][0] = lr[m][1] = 0.0f;
    }

    float4 kfa[2], kfb[2];       // K prefetch: 2 rows of 8 floats
    float4 vfa[2], vfb[2];       // V prefetch: rows 2k2, 2k2+1 x 8 floats

    auto prefetch = [&](int t) {
        const int t0 = split * KEYS_PER_SPLIT + t * KTILE;
        kfa[0] = *reinterpret_cast<const float4*>(&kb[(long)(t0 + kkey0) * HDIM + kc0 * 8]);
        kfb[0] = *reinterpret_cast<const float4*>(&kb[(long)(t0 + kkey0) * HDIM + kc0 * 8 + 4]);
        kfa[1] = *reinterpret_cast<const float4*>(&kb[(long)(t0 + kkey1) * HDIM + kc1 * 8]);
        kfb[1] = *reinterpret_cast<const float4*>(&kb[(long)(t0 + kkey1) * HDIM + kc1 * 8 + 4]);
        vfa[0] = *reinterpret_cast<const float4*>(&vb[(long)(t0 + 2 * vk2) * HDIM + vh8]);
        vfa[1] = *reinterpret_cast<const float4*>(&vb[(long)(t0 + 2 * vk2) * HDIM + vh8 + 4]);
        vfb[0] = *reinterpret_cast<const float4*>(&vb[(long)(t0 + 2 * vk2 + 1) * HDIM + vh8]);
        vfb[1] = *reinterpret_cast<const float4*>(&vb[(long)(t0 + 2 * vk2 + 1) * HDIM + vh8 + 4]);
    };
    auto write_tile = [&]() {
        // K: entry [key][4*kap+tg], field (c&1): h2(cols 16kap+2tg(+8), +1)
        #pragma unroll
        for (int p = 0; p < 2; p++) {
            const int key = p ? kkey1 : kkey0;
            const int c   = p ? kc1 : kc0;
            float4 fa = kfa[p], fb = kfb[p];
            float f[8] = {fa.x, fa.y, fa.z, fa.w, fb.x, fb.y, fb.z, fb.w};
            const int kap = c >> 1, cb = c & 1;
            #pragma unroll
            for (int t2 = 0; t2 < 4; t2++) {
                const int idx = key * KVSTRU2 + kap * 4 + t2;
                reinterpret_cast<uint32*>(&Kh[idx])[cb] = pkh2(f[2 * t2], f[2 * t2 + 1]);
                reinterpret_cast<uint32*>(&Kl[idx])[cb] =
                    pkh2(f16lo(f[2 * t2]), f16lo(f[2 * t2 + 1]));
            }
        }
        // V: entry [h][4*kap+tg], field: pair of adjacent keys
        {
            float va[8] = {vfa[0].x, vfa[0].y, vfa[0].z, vfa[0].w,
                           vfa[1].x, vfa[1].y, vfa[1].z, vfa[1].w};
            float vb_[8] = {vfb[0].x, vfb[0].y, vfb[0].z, vfb[0].w,
                            vfb[1].x, vfb[1].y, vfb[1].z, vfb[1].w};
            const int kap = vk2 >> 3, r = vk2 & 7;
            const int cb = r >> 2, tt = r & 3;
            #pragma unroll
            for (int j = 0; j < 8; j++) {
                const int h = vh8 + j;
                reinterpret_cast<uint32*>(&Vh[h * KVSTRU2 + kap * 4 + tt])[cb] =
                    pkh2(va[j], vb_[j]);
            }
        }
    };

    prefetch(0);

    #pragma unroll 1
    for (int t = 0; t < NT; t++) {
        __syncthreads();
        write_tile();
        __syncthreads();
        if (t + 1 < NT) prefetch(t + 1);

        // ---- QK: S = Q K^T, 3-term fp16 split ----
        float s[2][4][4];
        #pragma unroll
        for (int m = 0; m < 2; m++)
            #pragma unroll
            for (int n = 0; n < 4; n++)
                #pragma unroll
                for (int i = 0; i < 4; i++) s[m][n][i] = 0.0f;

        #pragma unroll
        for (int kap = 0; kap < 4; kap++) {
            uint4 qh[2], ql[2];
            #pragma unroll
            for (int m = 0; m < 2; m++) {
                const int idx = (w * 2 + m) * 128 + kap * 32 + g * 4 + tg;
                qh[m] = QAh[idx];
                ql[m] = QAl[idx];
            }
            #pragma unroll
            for (int n = 0; n < 4; n++) {
                const int kidx = (8 * n + g) * KVSTRU2 + kap * 4 + tg;
                uint2 kh = Kh[kidx];
                uint2 kl = Kl[kidx];
                #pragma unroll
                for (int m = 0; m < 2; m++) {
                    mma_f16(s[m][n][0], s[m][n][1], s[m][n][2], s[m][n][3],
                            qh[m].x, qh[m].y, qh[m].z, qh[m].w, kh.x, kh.y);
                    mma_f16(s[m][n][0], s[m][n][1], s[m][n][2], s[m][n][3],
                            ql[m].x, ql[m].y, ql[m].z, ql[m].w, kh.x, kh.y);
                    mma_f16(s[m][n][0], s[m][n][1], s[m][n][2], s[m][n][3],
                            qh[m].x, qh[m].y, qh[m].z, qh[m].w, kl.x, kl.y);
                }
            }
        }

        // ---- online softmax ----
        #pragma unroll
        for (int m = 0; m < 2; m++) {
            const int mb = w * 2 + m;
            float mxA = -1e30f, mxB = -1e30f;
            #pragma unroll
            for (int n = 0; n < 4; n++) {
                mxA = fmaxf(mxA, fmaxf(s[m][n][0], s[m][n][1]));
                mxB = fmaxf(mxB, fmaxf(s[m][n][2], s[m][n][3]));
            }
            mxA = fmaxf(mxA, __shfl_xor_sync(0xffffffffu, mxA, 1));
            mxA = fmaxf(mxA, __shfl_xor_sync(0xffffffffu, mxA, 2));
            mxB = fmaxf(mxB, __shfl_xor_sync(0xffffffffu, mxB, 1));
            mxB = fmaxf(mxB, __shfl_xor_sync(0xffffffffu, mxB, 2));

            const float nmA = fmaxf(mr[m][0], mxA);
            const float nmB = fmaxf(mr[m][1], mxB);
            const float alA = __expf(mr[m][0] - nmA);
            const float alB = __expf(mr[m][1] - nmB);
            mr[m][0] = nmA; mr[m][1] = nmB;

            float lsA = 0.0f, lsB = 0.0f;
            #pragma unroll
            for (int n = 0; n < 4; n++) {
                float p0 = __expf(s[m][n][0] - nmA);
                float p1 = __expf(s[m][n][1] - nmA);
                float p2 = __expf(s[m][n][2] - nmB);
                float p3 = __expf(s[m][n][3] - nmB);
                lsA += p0 + p1;
                lsB += p2 + p3;
                P2h[mb * 192 + (4 * n + tg) * PSTRU2 + g] =
                    make_uint2(pkh2(p0, p1), pkh2(p2, p3));
            }
            lsA += __shfl_xor_sync(0xffffffffu, lsA, 1);
            lsA += __shfl_xor_sync(0xffffffffu, lsA, 2);
            lsB += __shfl_xor_sync(0xffffffffu, lsB, 1);
            lsB += __shfl_xor_sync(0xffffffffu, lsB, 2);
            lr[m][0] = lr[m][0] * alA + lsA;
            lr[m][1] = lr[m][1] * alB + lsB;

            #pragma unroll
            for (int n = 0; n < 8; n++) {
                o[m][n][0] *= alA; o[m][n][1] *= alA;
                o[m][n][2] *= alB; o[m][n][3] *= alB;
            }
        }
        __syncwarp();

        // ---- PV: O += P V (1x fp16) ----
        #pragma unroll
        for (int kap = 0; kap < 2; kap++) {
            uint2 pa[2], pb[2];
            #pragma unroll
            for (int m = 0; m < 2; m++) {
                const int mb = w * 2 + m;
                pa[m] = P2h[mb * 192 + (8 * kap + tg) * PSTRU2 + g];
                pb[m] = P2h[mb * 192 + (8 * kap + tg + 4) * PSTRU2 + g];
            }
            #pragma unroll
            for (int n = 0; n < 8; n++) {
                uint2 vp = Vh[(8 * n + g) * KVSTRU2 + kap * 4 + tg];
                #pragma unroll
                for (int m = 0; m < 2; m++) {
                    mma_f16(o[m][n][0], o[m][n][1], o[m][n][2], o[m][n][3],
                            pa[m].x, pa[m].y, pb[m].x, pb[m].y, vp.x, vp.y);
                }
            }
        }
    }

    // ---- epilogue: write unnormalized partials + (m, l) ----
    #pragma unroll
    for (int m = 0; m < 2; m++) {
        const long rowA = (long)b * TSEQ + q0 + w * 32 + m * 16 + g;
        const long rowB = rowA + 8;
        #pragma unroll
        for (int n = 0; n < 8; n++) {
            const int c = n * 8 + 2 * tg;
            *reinterpret_cast<float2*>(&g_pacc[split][rowA][c]) =
                make_float2(o[m][n][0], o[m][n][1]);
            *reinterpret_cast<float2*>(&g_pacc[split][rowB][c]) =
                make_float2(o[m][n][2], o[m][n][3]);
        }
        if (tg == 0) {
            g_pm[split][rowA] = mr[m][0];
            g_pl[split][rowA] = lr[m][0];
            g_pm[split][rowB] = mr[m][1];
            g_pl[split][rowB] = lr[m][1];
        }
    }
}

// ---------------------------------------------------------------------------
// Combine split-KV partials.
// ---------------------------------------------------------------------------
__global__ __launch_bounds__(128) void combine_kernel(float* __restrict__ out)
{
    const long row = (long)blockIdx.x * 128 + threadIdx.x;

    float m[NSPLIT], w[NSPLIT];
    float M = -1e30f;
    #pragma unroll
    for (int i = 0; i < NSPLIT; i++) {
        m[i] = g_pm[i][row];
        M = fmaxf(M, m[i]);
    }
    float L = 0.0f;
    #pragma unroll
    for (int i = 0; i < NSPLIT; i++) {
        w[i] = __expf(m[i] - M);
        L += w[i] * g_pl[i][row];
    }
    const float inv = 1.0f / L;

    float* __restrict__ orow = &out[row * HDIM];
    #pragma unroll
    for (int h = 0; h < HDIM; h += 4) {
        float4 a = make_float4(0.f, 0.f, 0.f, 0.f);
        #pragma unroll
        for (int i = 0; i < NSPLIT; i++) {
            float4 p = *reinterpret_cast<const float4*>(&g_pacc[i][row][h]);
            a.x += w[i] * p.x;
            a.y += w[i] * p.y;
            a.z += w[i] * p.z;
            a.w += w[i] * p.w;
        }
        a.x *= inv; a.y *= inv; a.z *= inv; a.w *= inv;
        *reinterpret_cast<float4*>(&orow[h]) = a;
    }
}

// ---------------------------------------------------------------------------
extern "C" void kernel_launch(void* const* d_in, const int* in_sizes, int n_in,
                              void* d_out, int out_size)
{
    const float* x  = (const float*)d_in[0];
    const float* Wq = (const float*)d_in[1];
    const float* Wk = (const float*)d_in[2];
    const float* Wv = (const float*)d_in[3];
    float* out = (float*)d_out;

    transpose_w_kernel<<<dim3(128, 3), 256>>>(Wq, Wk, Wv);

    proj_mma_kernel<<<dim3(BT_TOTAL / 128, 3), 128>>>(x);

    const int smem_bytes = 65536;
    static bool attr_set = false;
    if (!attr_set) {
        cudaFuncSetAttribute(attn_mma_kernel,
                             cudaFuncAttributeMaxDynamicSharedMemorySize, smem_bytes);
        attr_set = true;
    }
    dim3 ag(TSEQ / QTILE, BATCH, NSPLIT);
    attn_mma_kernel<<<ag, 128, smem_bytes>>>();

    combine_kernel<<<BT_TOTAL / 128, 128>>>(out);
}

// round 15
// speedup vs baseline: 2.0676x; 1.1052x over previous
#include <cuda_runtime.h>
#include <cuda_fp16.h>
#include <cstdint>

#define BATCH   4
#define TSEQ    4096
#define CDIM    512
#define HDIM    64
#define BT_TOTAL (BATCH * TSEQ)   // 16384
#define QTILE   128
#define KTILE   32
#define NSPLIT  2
#define KEYS_PER_SPLIT (TSEQ / NSPLIT)     // 2048
#define NT      (KEYS_PER_SPLIT / KTILE)   // 64

#define KVSTRU2 20   // K/V/W row stride in uint2 (16 used)
#define PSTRU2  12   // P row stride in uint2 (8 used)
#define XSTR    36   // xs row stride (floats)

typedef unsigned int uint32;

// ---- fp16 helpers ----
__device__ __forceinline__ uint32 pkh2(float a, float b) {
    __half2 h = __floats2half2_rn(a, b);
    return *reinterpret_cast<uint32*>(&h);
}
__device__ __forceinline__ float f16lo(float a) {
    return a - __half2float(__float2half_rn(a));
}
__device__ __forceinline__ void mma_f16(
    float& c0, float& c1, float& c2, float& c3,
    uint32 a0, uint32 a1, uint32 a2, uint32 a3,
    uint32 b0, uint32 b1)
{
    asm("mma.sync.aligned.m16n8k16.row.col.f32.f16.f16.f32 "
        "{%0,%1,%2,%3},{%4,%5,%6,%7},{%8,%9},{%0,%1,%2,%3};"
        : "+f"(c0), "+f"(c1), "+f"(c2), "+f"(c3)
        : "r"(a0), "r"(a1), "r"(a2), "r"(a3), "r"(b0), "r"(b1));
}

// Scratch (static device arrays per allocation rules).
__device__ float g_q[BT_TOTAL * HDIM];
__device__ float g_k[BT_TOTAL * HDIM];
__device__ float g_v[BT_TOTAL * HDIM];
__device__ uint32 g_wh[3][HDIM][CDIM / 2];   // W^T hi, half2-packed along k
__device__ uint32 g_wl[3][HDIM][CDIM / 2];   // W^T lo
// split-KV partials
__device__ float g_pacc[NSPLIT][BT_TOTAL][HDIM];
__device__ float g_pm[NSPLIT][BT_TOTAL];
__device__ float g_pl[NSPLIT][BT_TOTAL];

// ---------------------------------------------------------------------------
// Transpose + hi/lo split W [512][64] -> g_wh/g_wl [64][256] half2.
// grid (64, 3), block 256.
// ---------------------------------------------------------------------------
__global__ __launch_bounds__(256) void transpose_w_kernel(
    const float* __restrict__ Wq,
    const float* __restrict__ Wk,
    const float* __restrict__ Wv)
{
    const int mat = blockIdx.y;
    const float* __restrict__ W = (mat == 0) ? Wq : (mat == 1) ? Wk : Wv;
    const int idx = blockIdx.x * 256 + threadIdx.x;   // 0..16383
    const int k2  = idx & (CDIM / 2 - 1);
    const int n   = idx >> 8;
    const float w0 = W[(2 * k2) * HDIM + n];
    const float w1 = W[(2 * k2 + 1) * HDIM + n];
    g_wh[mat][n][k2] = pkh2(w0, w1);
    g_wl[mat][n][k2] = pkh2(f16lo(w0), f16lo(w1));
}

// ---------------------------------------------------------------------------
// Projection GEMM on fp16 HMMA m16n8k16, 3-term split (== 3xTF32 accuracy).
// out[16384,64] = x[16384,512] @ W[512,64], x3. Q scaled by 8.
// grid (BT/128, 3), block 128 (4 warps x m32 rows).
// ---------------------------------------------------------------------------
__global__ __launch_bounds__(128) void proj_mma_kernel(const float* __restrict__ x)
{
    __shared__ float xs[128 * XSTR];           // raw x tile [128][32]
    __shared__ uint2 Whs[HDIM * KVSTRU2];      // W hi B-frags (attn-K layout)
    __shared__ uint2 Wls[HDIM * KVSTRU2];      // W lo B-frags

    const int mat  = blockIdx.y;
    float* __restrict__ out = (mat == 0) ? g_q : (mat == 1) ? g_k : g_v;
    const int row0 = blockIdx.x * 128;
    const int tid  = threadIdx.x;
    const int w    = tid >> 5;
    const int ln   = tid & 31;
    const int g    = ln >> 2;
    const int tg   = ln & 3;

    float o[2][8][4];
    #pragma unroll
    for (int m = 0; m < 2; m++)
        #pragma unroll
        for (int n = 0; n < 8; n++)
            #pragma unroll
            for (int i = 0; i < 4; i++) o[m][n][i] = 0.0f;

    #pragma unroll 1
    for (int k0 = 0; k0 < CDIM; k0 += 32) {
        __syncthreads();
        // ---- stage x raw: 1024 float4 tasks, 8 per thread ----
        #pragma unroll
        for (int p = 0; p < 8; p++) {
            const int task = p * 128 + tid;
            const int r    = task >> 3;
            const int cg   = task & 7;
            float4 v = *reinterpret_cast<const float4*>(
                &x[(long)(row0 + r) * CDIM + k0 + cg * 4]);
            *reinterpret_cast<float4*>(&xs[r * XSTR + cg * 4]) = v;
        }
        // ---- stage W hi/lo B-frags: 512 uint2 each, 4 per thread ----
        #pragma unroll
        for (int p = 0; p < 4; p++) {
            const int task = p * 128 + tid;
            const int n    = task >> 3;
            const int j    = task & 7;
            const int kap  = j >> 2;
            const int t2   = j & 3;
            const int src  = (k0 >> 1) + kap * 8 + t2;
            const int dst  = n * KVSTRU2 + kap * 4 + t2;
            Whs[dst] = make_uint2(g_wh[mat][n][src], g_wh[mat][n][src + 4]);
            Wls[dst] = make_uint2(g_wl[mat][n][src], g_wl[mat][n][src + 4]);
        }
        __syncthreads();

        // ---- mma mainloop: 2 kap x 8 n x 2 m x 3 products ----
        #pragma unroll
        for (int kap = 0; kap < 2; kap++) {
            uint4 ah[2], al[2];
            #pragma unroll
            for (int m = 0; m < 2; m++) {
                const int r = w * 32 + m * 16 + g;
                const int c = kap * 16 + 2 * tg;
                float2 a00 = *reinterpret_cast<const float2*>(&xs[r * XSTR + c]);
                float2 a10 = *reinterpret_cast<const float2*>(&xs[(r + 8) * XSTR + c]);
                float2 a01 = *reinterpret_cast<const float2*>(&xs[r * XSTR + c + 8]);
                float2 a11 = *reinterpret_cast<const float2*>(&xs[(r + 8) * XSTR + c + 8]);
                ah[m] = make_uint4(pkh2(a00.x, a00.y), pkh2(a10.x, a10.y),
                                   pkh2(a01.x, a01.y), pkh2(a11.x, a11.y));
                al[m] = make_uint4(pkh2(f16lo(a00.x), f16lo(a00.y)),
                                   pkh2(f16lo(a10.x), f16lo(a10.y)),
                                   pkh2(f16lo(a01.x), f16lo(a01.y)),
                                   pkh2(f16lo(a11.x), f16lo(a11.y)));
            }
            #pragma unroll
            for (int n = 0; n < 8; n++) {
                const int widx = (n * 8 + g) * KVSTRU2 + kap * 4 + tg;
                uint2 wh = Whs[widx];
                uint2 wl = Wls[widx];
                #pragma unroll
                for (int m = 0; m < 2; m++) {
                    mma_f16(o[m][n][0], o[m][n][1], o[m][n][2], o[m][n][3],
                            ah[m].x, ah[m].y, ah[m].z, ah[m].w, wh.x, wh.y);
                    mma_f16(o[m][n][0], o[m][n][1], o[m][n][2], o[m][n][3],
                            al[m].x, al[m].y, al[m].z, al[m].w, wh.x, wh.y);
                    mma_f16(o[m][n][0], o[m][n][1], o[m][n][2], o[m][n][3],
                            ah[m].x, ah[m].y, ah[m].z, ah[m].w, wl.x, wl.y);
                }
            }
        }
    }

    const float scale = (mat == 0) ? 8.0f : 1.0f;
    #pragma unroll
    for (int m = 0; m < 2; m++) {
        const long rowA = (long)(row0 + w * 32 + m * 16 + g);
        const long rowB = rowA + 8;
        #pragma unroll
        for (int n = 0; n < 8; n++) {
            const int c = n * 8 + 2 * tg;
            *reinterpret_cast<float2*>(&out[rowA * HDIM + c]) =
                make_float2(o[m][n][0] * scale, o[m][n][1] * scale);
            *reinterpret_cast<float2*>(&out[rowB * HDIM + c]) =
                make_float2(o[m][n][2] * scale, o[m][n][3] * scale);
        }
    }
}

// ---------------------------------------------------------------------------
// Flash attention on fp16 HMMA m16n8k16 (unchanged from R14 except the
// alpha-guarded O-rescale). QK = 3-term fp16 split, PV = 1x fp16.
// ---------------------------------------------------------------------------
__global__ __launch_bounds__(128) void attn_mma_kernel()
{
    extern __shared__ uint4 smu[];
    uint4* QAh = smu;                                      // 1024 uint4
    uint4* QAl = smu + 1024;                               // 1024 uint4
    uint2* Kh  = reinterpret_cast<uint2*>(smu + 2048);     // 640 uint2
    uint2* Kl  = Kh + 640;                                 // 640
    uint2* Vh  = Kl + 640;                                 // 1280
    uint2* P2h = Vh + 1280;                                // 1536

    const int b     = blockIdx.y;
    const int split = blockIdx.z;
    const int q0    = blockIdx.x * QTILE;
    const int tid   = threadIdx.x;
    const int w     = tid >> 5;
    const int ln    = tid & 31;
    const int g     = ln >> 2;
    const int tg    = ln & 3;

    const float* __restrict__ kb = &g_k[(long)b * TSEQ * HDIM];
    const float* __restrict__ vb = &g_v[(long)b * TSEQ * HDIM];

    const int kkey0 = tid >> 3, kc0 = tid & 7;
    const int kkey1 = (128 + tid) >> 3, kc1 = (128 + tid) & 7;
    const int vk2 = tid >> 3;
    const int vh8 = (tid & 7) * 8;

    // ---- stage Q ----
    #pragma unroll
    for (int i = 0; i < 8; i++) {
        const int e   = tid * 8 + i;
        const int mb  = e >> 7;
        const int kap = (e >> 5) & 3;
        const int gg  = (e >> 2) & 7;
        const int tt  = e & 3;
        const int r   = (mb >> 1) * 32 + (mb & 1) * 16 + gg;
        const int c   = kap * 16 + 2 * tt;
        const float* r0p = &g_q[((long)b * TSEQ + q0 + r) * HDIM];
        const float* r1p = &g_q[((long)b * TSEQ + q0 + r + 8) * HDIM];
        float2 q00 = *reinterpret_cast<const float2*>(&r0p[c]);
        float2 q10 = *reinterpret_cast<const float2*>(&r1p[c]);
        float2 q01 = *reinterpret_cast<const float2*>(&r0p[c + 8]);
        float2 q11 = *reinterpret_cast<const float2*>(&r1p[c + 8]);
        QAh[e] = make_uint4(pkh2(q00.x, q00.y), pkh2(q10.x, q10.y),
                            pkh2(q01.x, q01.y), pkh2(q11.x, q11.y));
        QAl[e] = make_uint4(pkh2(f16lo(q00.x), f16lo(q00.y)),
                            pkh2(f16lo(q10.x), f16lo(q10.y)),
                            pkh2(f16lo(q01.x), f16lo(q01.y)),
                            pkh2(f16lo(q11.x), f16lo(q11.y)));
    }

    float o[2][8][4];
    #pragma unroll
    for (int m = 0; m < 2; m++)
        #pragma unroll
        for (int n = 0; n < 8; n++)
            #pragma unroll
            for (int i = 0; i < 4; i++) o[m][n][i] = 0.0f;
    float mr[2][2], lr[2][2];
    #pragma unroll
    for (int m = 0; m < 2; m++) {
        mr[m][0] = mr[m][1] = -1e30f;
        lr[m][0] = lr[m][1] = 0.0f;
    }

    float4 kfa[2], kfb[2], vfa[2], vfb[2];

    auto prefetch = [&](int t) {
        const int t0 = split * KEYS_PER_SPLIT + t * KTILE;
        kfa[0] = *reinterpret_cast<const float4*>(&kb[(long)(t0 + kkey0) * HDIM + kc0 * 8]);
        kfb[0] = *reinterpret_cast<const float4*>(&kb[(long)(t0 + kkey0) * HDIM + kc0 * 8 + 4]);
        kfa[1] = *reinterpret_cast<const float4*>(&kb[(long)(t0 + kkey1) * HDIM + kc1 * 8]);
        kfb[1] = *reinterpret_cast<const float4*>(&kb[(long)(t0 + kkey1) * HDIM + kc1 * 8 + 4]);
        vfa[0] = *reinterpret_cast<const float4*>(&vb[(long)(t0 + 2 * vk2) * HDIM + vh8]);
        vfa[1] = *reinterpret_cast<const float4*>(&vb[(long)(t0 + 2 * vk2) * HDIM + vh8 + 4]);
        vfb[0] = *reinterpret_cast<const float4*>(&vb[(long)(t0 + 2 * vk2 + 1) * HDIM + vh8]);
        vfb[1] = *reinterpret_cast<const float4*>(&vb[(long)(t0 + 2 * vk2 + 1) * HDIM + vh8 + 4]);
    };
    auto write_tile = [&]() {
        #pragma unroll
        for (int p = 0; p < 2; p++) {
            const int key = p ? kkey1 : kkey0;
            const int c   = p ? kc1 : kc0;
            float4 fa = kfa[p], fb = kfb[p];
            float f[8] = {fa.x, fa.y, fa.z, fa.w, fb.x, fb.y, fb.z, fb.w};
            const int kap = c >> 1, cb = c & 1;
            #pragma unroll
            for (int t2 = 0; t2 < 4; t2++) {
                const int idx = key * KVSTRU2 + kap * 4 + t2;
                reinterpret_cast<uint32*>(&Kh[idx])[cb] = pkh2(f[2 * t2], f[2 * t2 + 1]);
                reinterpret_cast<uint32*>(&Kl[idx])[cb] =
                    pkh2(f16lo(f[2 * t2]), f16lo(f[2 * t2 + 1]));
            }
        }
        {
            float va[8] = {vfa[0].x, vfa[0].y, vfa[0].z, vfa[0].w,
                           vfa[1].x, vfa[1].y, vfa[1].z, vfa[1].w};
            float vb_[8] = {vfb[0].x, vfb[0].y, vfb[0].z, vfb[0].w,
                            vfb[1].x, vfb[1].y, vfb[1].z, vfb[1].w};
            const int kap = vk2 >> 3, r = vk2 & 7;
            const int cb = r >> 2, tt = r & 3;
            #pragma unroll
            for (int j = 0; j < 8; j++) {
                const int h = vh8 + j;
                reinterpret_cast<uint32*>(&Vh[h * KVSTRU2 + kap * 4 + tt])[cb] =
                    pkh2(va[j], vb_[j]);
            }
        }
    };

    prefetch(0);

    #pragma unroll 1
    for (int t = 0; t < NT; t++) {
        __syncthreads();
        write_tile();
        __syncthreads();
        if (t + 1 < NT) prefetch(t + 1);

        // ---- QK: S = Q K^T, 3-term fp16 split ----
        float s[2][4][4];
        #pragma unroll
        for (int m = 0; m < 2; m++)
            #pragma unroll
            for (int n = 0; n < 4; n++)
                #pragma unroll
                for (int i = 0; i < 4; i++) s[m][n][i] = 0.0f;

        #pragma unroll
        for (int kap = 0; kap < 4; kap++) {
            uint4 qh[2], ql[2];
            #pragma unroll
            for (int m = 0; m < 2; m++) {
                const int idx = (w * 2 + m) * 128 + kap * 32 + g * 4 + tg;
                qh[m] = QAh[idx];
                ql[m] = QAl[idx];
            }
            #pragma unroll
            for (int n = 0; n < 4; n++) {
                const int kidx = (8 * n + g) * KVSTRU2 + kap * 4 + tg;
                uint2 kh = Kh[kidx];
                uint2 kl = Kl[kidx];
                #pragma unroll
                for (int m = 0; m < 2; m++) {
                    mma_f16(s[m][n][0], s[m][n][1], s[m][n][2], s[m][n][3],
                            qh[m].x, qh[m].y, qh[m].z, qh[m].w, kh.x, kh.y);
                    mma_f16(s[m][n][0], s[m][n][1], s[m][n][2], s[m][n][3],
                            ql[m].x, ql[m].y, ql[m].z, ql[m].w, kh.x, kh.y);
                    mma_f16(s[m][n][0], s[m][n][1], s[m][n][2], s[m][n][3],
                            qh[m].x, qh[m].y, qh[m].z, qh[m].w, kl.x, kl.y);
                }
            }
        }

        // ---- online softmax ----
        #pragma unroll
        for (int m = 0; m < 2; m++) {
            const int mb = w * 2 + m;
            float mxA = -1e30f, mxB = -1e30f;
            #pragma unroll
            for (int n = 0; n < 4; n++) {
                mxA = fmaxf(mxA, fmaxf(s[m][n][0], s[m][n][1]));
                mxB = fmaxf(mxB, fmaxf(s[m][n][2], s[m][n][3]));
            }
            mxA = fmaxf(mxA, __shfl_xor_sync(0xffffffffu, mxA, 1));
            mxA = fmaxf(mxA, __shfl_xor_sync(0xffffffffu, mxA, 2));
            mxB = fmaxf(mxB, __shfl_xor_sync(0xffffffffu, mxB, 1));
            mxB = fmaxf(mxB, __shfl_xor_sync(0xffffffffu, mxB, 2));

            const float nmA = fmaxf(mr[m][0], mxA);
            const float nmB = fmaxf(mr[m][1], mxB);
            const float alA = __expf(mr[m][0] - nmA);
            const float alB = __expf(mr[m][1] - nmB);
            mr[m][0] = nmA; mr[m][1] = nmB;

            float lsA = 0.0f, lsB = 0.0f;
            #pragma unroll
            for (int n = 0; n < 4; n++) {
                float p0 = __expf(s[m][n][0] - nmA);
                float p1 = __expf(s[m][n][1] - nmA);
                float p2 = __expf(s[m][n][2] - nmB);
                float p3 = __expf(s[m][n][3] - nmB);
                lsA += p0 + p1;
                lsB += p2 + p3;
                P2h[mb * 192 + (4 * n + tg) * PSTRU2 + g] =
                    make_uint2(pkh2(p0, p1), pkh2(p2, p3));
            }
            lsA += __shfl_xor_sync(0xffffffffu, lsA, 1);
            lsA += __shfl_xor_sync(0xffffffffu, lsA, 2);
            lsB += __shfl_xor_sync(0xffffffffu, lsB, 1);
            lsB += __shfl_xor_sync(0xffffffffu, lsB, 2);
            lr[m][0] = lr[m][0] * alA + lsA;
            lr[m][1] = lr[m][1] * alB + lsB;

            // O-rescale only when some row's running max actually moved
            // (record-update statistics: ~5 of 64 tiles).
            if (__any_sync(0xffffffffu, (alA != 1.0f) || (alB != 1.0f))) {
                #pragma unroll
                for (int n = 0; n < 8; n++) {
                    o[m][n][0] *= alA; o[m][n][1] *= alA;
                    o[m][n][2] *= alB; o[m][n][3] *= alB;
                }
            }
        }
        __syncwarp();

        // ---- PV: O += P V (1x fp16) ----
        #pragma unroll
        for (int kap = 0; kap < 2; kap++) {
            uint2 pa[2], pb[2];
            #pragma unroll
            for (int m = 0; m < 2; m++) {
                const int mb = w * 2 + m;
                pa[m] = P2h[mb * 192 + (8 * kap + tg) * PSTRU2 + g];
                pb[m] = P2h[mb * 192 + (8 * kap + tg + 4) * PSTRU2 + g];
            }
            #pragma unroll
            for (int n = 0; n < 8; n++) {
                uint2 vp = Vh[(8 * n + g) * KVSTRU2 + kap * 4 + tg];
                #pragma unroll
                for (int m = 0; m < 2; m++) {
                    mma_f16(o[m][n][0], o[m][n][1], o[m][n][2], o[m][n][3],
                            pa[m].x, pa[m].y, pb[m].x, pb[m].y, vp.x, vp.y);
                }
            }
        }
    }

    // ---- epilogue ----
    #pragma unroll
    for (int m = 0; m < 2; m++) {
        const long rowA = (long)b * TSEQ + q0 + w * 32 + m * 16 + g;
        const long rowB = rowA + 8;
        #pragma unroll
        for (int n = 0; n < 8; n++) {
            const int c = n * 8 + 2 * tg;
            *reinterpret_cast<float2*>(&g_pacc[split][rowA][c]) =
                make_float2(o[m][n][0], o[m][n][1]);
            *reinterpret_cast<float2*>(&g_pacc[split][rowB][c]) =
                make_float2(o[m][n][2], o[m][n][3]);
        }
        if (tg == 0) {
            g_pm[split][rowA] = mr[m][0];
            g_pl[split][rowA] = lr[m][0];
            g_pm[split][rowB] = mr[m][1];
            g_pl[split][rowB] = lr[m][1];
        }
    }
}

// ---------------------------------------------------------------------------
// Combine split-KV partials.
// ---------------------------------------------------------------------------
__global__ __launch_bounds__(128) void combine_kernel(float* __restrict__ out)
{
    const long row = (long)blockIdx.x * 128 + threadIdx.x;

    float m[NSPLIT], w[NSPLIT];
    float M = -1e30f;
    #pragma unroll
    for (int i = 0; i < NSPLIT; i++) {
        m[i] = g_pm[i][row];
        M = fmaxf(M, m[i]);
    }
    float L = 0.0f;
    #pragma unroll
    for (int i = 0; i < NSPLIT; i++) {
        w[i] = __expf(m[i] - M);
        L += w[i] * g_pl[i][row];
    }
    const float inv = 1.0f / L;

    float* __restrict__ orow = &out[row * HDIM];
    #pragma unroll
    for (int h = 0; h < HDIM; h += 4) {
        float4 a = make_float4(0.f, 0.f, 0.f, 0.f);
        #pragma unroll
        for (int i = 0; i < NSPLIT; i++) {
            float4 p = *reinterpret_cast<const float4*>(&g_pacc[i][row][h]);
            a.x += w[i] * p.x;
            a.y += w[i] * p.y;
            a.z += w[i] * p.z;
            a.w += w[i] * p.w;
        }
        a.x *= inv; a.y *= inv; a.z *= inv; a.w *= inv;
        *reinterpret_cast<float4*>(&orow[h]) = a;
    }
}

// ---------------------------------------------------------------------------
extern "C" void kernel_launch(void* const* d_in, const int* in_sizes, int n_in,
                              void* d_out, int out_size)
{
    const float* x  = (const float*)d_in[0];
    const float* Wq = (const float*)d_in[1];
    const float* Wk = (const float*)d_in[2];
    const float* Wv = (const float*)d_in[3];
    float* out = (float*)d_out;

    transpose_w_kernel<<<dim3(64, 3), 256>>>(Wq, Wk, Wv);

    proj_mma_kernel<<<dim3(BT_TOTAL / 128, 3), 128>>>(x);

    const int smem_bytes = 65536;
    static bool attr_set = false;
    if (!attr_set) {
        cudaFuncSetAttribute(attn_mma_kernel,
                             cudaFuncAttributeMaxDynamicSharedMemorySize, smem_bytes);
        attr_set = true;
    }
    dim3 ag(TSEQ / QTILE, BATCH, NSPLIT);
    attn_mma_kernel<<<ag, 128, smem_bytes>>>();

    combine_kernel<<<BT_TOTAL / 128, 128>>>(out);
}